// round 3
// baseline (speedup 1.0000x reference)
#include <cuda_runtime.h>
#include <math.h>

// ---------------------------------------------------------------------------
// Problem constants
// ---------------------------------------------------------------------------
#define B_   64
#define P_   225
#define K_   16
#define D_   640
#define MQ   (B_ * P_)      // 14400 query rows
#define NR   (K_ * P_)      // 3600 reference rows

// ---------------------------------------------------------------------------
// Scratch (allocation-free: __device__ globals)
// ---------------------------------------------------------------------------
__device__ float g_qn[MQ * D_];      // normalized q_patch
__device__ float g_rn[NR * D_];      // normalized r_patch
__device__ float g_amap[MQ];         // 0.5*(1 - max sim)
__device__ float g_famean[D_];       // mean adapter output

// ---------------------------------------------------------------------------
// Kernel 1: row L2-normalize (x / (||x|| + 1e-6)), D=640 per row
// ---------------------------------------------------------------------------
__global__ void norm_rows_kernel(const float* __restrict__ in,
                                 float* __restrict__ out) {
    const int row = blockIdx.x;
    const float* x = in + (size_t)row * D_;
    float ss = 0.f;
    for (int i = threadIdx.x; i < D_; i += blockDim.x) {
        float v = x[i];
        ss = fmaf(v, v, ss);
    }
    // warp reduce
    #pragma unroll
    for (int o = 16; o > 0; o >>= 1) ss += __shfl_xor_sync(0xffffffffu, ss, o);
    __shared__ float wsum[4];
    const int lane = threadIdx.x & 31, warp = threadIdx.x >> 5;
    if (lane == 0) wsum[warp] = ss;
    __syncthreads();
    float total = wsum[0] + wsum[1] + wsum[2] + wsum[3];
    const float scale = 1.f / (sqrtf(total) + 1e-6f);
    float* o = out + (size_t)row * D_;
    for (int i = threadIdx.x; i < D_; i += blockDim.x)
        o[i] = x[i] * scale;
}

// ---------------------------------------------------------------------------
// Kernel 2: fused GEMM + row-max: amap[m] = 0.5*(1 - max_n dot(qn[m], rn[n]))
// 64x64 block tile, 4x4 per-thread micro-tile, BK=32, float4 smem reads.
// ---------------------------------------------------------------------------
#define BM 64
#define BN 64
#define BK 32
#define NT ((NR + BN - 1) / BN)   // 57
#define KT (D_ / BK)              // 20

__global__ __launch_bounds__(256, 2)
void gemm_max_kernel() {
    __shared__ __align__(16) float As[BK][BM + 4];
    __shared__ __align__(16) float Bs[BK][BN + 4];

    const int tx = threadIdx.x & 15;        // 0..15 -> N
    const int ty = threadIdx.x >> 4;        // 0..15 -> M
    const int rowBase = blockIdx.x * BM;

    float runmax[4] = {-1e30f, -1e30f, -1e30f, -1e30f};

    for (int nt = 0; nt < NT; ++nt) {
        const int nBase = nt * BN;
        float acc[4][4];
        #pragma unroll
        for (int i = 0; i < 4; ++i)
            #pragma unroll
            for (int j = 0; j < 4; ++j) acc[i][j] = 0.f;

        for (int kt = 0; kt < KT; ++kt) {
            const int k0 = kt * BK;
            // Load A tile (64x32) transposed into As[k][m], coalesced on k
            #pragma unroll
            for (int it = 0; it < 8; ++it) {
                int idx = threadIdx.x + it * 256;
                int m = idx >> 5, k = idx & 31;
                As[k][m] = g_qn[(size_t)(rowBase + m) * D_ + k0 + k];
            }
            // Load B tile (64x32) transposed, zero-pad rows >= NR
            #pragma unroll
            for (int it = 0; it < 8; ++it) {
                int idx = threadIdx.x + it * 256;
                int n = idx >> 5, k = idx & 31;
                int gn = nBase + n;
                Bs[k][n] = (gn < NR) ? g_rn[(size_t)gn * D_ + k0 + k] : 0.f;
            }
            __syncthreads();
            #pragma unroll
            for (int k = 0; k < BK; ++k) {
                float4 a4 = *(const float4*)&As[k][ty * 4];
                float4 b4 = *(const float4*)&Bs[k][tx * 4];
                float av[4] = {a4.x, a4.y, a4.z, a4.w};
                float bv[4] = {b4.x, b4.y, b4.z, b4.w};
                #pragma unroll
                for (int i = 0; i < 4; ++i)
                    #pragma unroll
                    for (int j = 0; j < 4; ++j)
                        acc[i][j] = fmaf(av[i], bv[j], acc[i][j]);
            }
            __syncthreads();
        }
        // fold this n-tile into running max (mask padded columns)
        #pragma unroll
        for (int j = 0; j < 4; ++j) {
            if (nBase + tx * 4 + j < NR) {
                #pragma unroll
                for (int i = 0; i < 4; ++i)
                    runmax[i] = fmaxf(runmax[i], acc[i][j]);
            }
        }
    }

    // cross-thread (over tx) max reduction per row
    __shared__ float red[BM][17];
    #pragma unroll
    for (int i = 0; i < 4; ++i) red[ty * 4 + i][tx] = runmax[i];
    __syncthreads();
    if (threadIdx.x < BM) {
        int r = threadIdx.x;
        float m = red[r][0];
        #pragma unroll
        for (int t = 1; t < 16; ++t) m = fmaxf(m, red[r][t]);
        g_amap[rowBase + r] = 0.5f * (1.f - m);
    }
}

// ---------------------------------------------------------------------------
// Kernel 3: adapter. famean = mean_k relu(relu(r_img @ w1) @ w2)
// r_img [16,640], w1 [640,160], w2 [160,640]
// ---------------------------------------------------------------------------
__global__ void adapter_kernel(const float* __restrict__ r_img,
                               const float* __restrict__ w1,
                               const float* __restrict__ w2) {
    __shared__ float h1[K_ * 160];
    for (int idx = threadIdx.x; idx < K_ * 160; idx += blockDim.x) {
        int k = idx / 160, i = idx % 160;
        float s = 0.f;
        const float* xr = r_img + k * D_;
        for (int d = 0; d < D_; ++d) s = fmaf(xr[d], w1[d * 160 + i], s);
        h1[idx] = fmaxf(s, 0.f);
    }
    __syncthreads();
    for (int j = threadIdx.x; j < D_; j += blockDim.x) {
        float acc = 0.f;
        for (int k = 0; k < K_; ++k) {
            float s = 0.f;
            const float* h = h1 + k * 160;
            for (int i = 0; i < 160; ++i) s = fmaf(h[i], w2[i * D_ + j], s);
            acc += fmaxf(s, 0.f);
        }
        g_famean[j] = acc * (1.f / (float)K_);
    }
}

// ---------------------------------------------------------------------------
// Kernel 4: both heads + final score, one block per batch element b.
// head(x): bn(relu(x@w1+b1),g2,be2) -> bn(relu(.@w2+b2),g3,be3) -> sigmoid(.@w3+b3)
// out[b] = 0.5*(s_ref + s_map) + mean_p amap[b,p]
// ---------------------------------------------------------------------------
__global__ void heads_kernel(
    const float* __restrict__ q_img,
    const float* __restrict__ dh_w1, const float* __restrict__ dh_b1,
    const float* __restrict__ dh_g2, const float* __restrict__ dh_be2,
    const float* __restrict__ dh_w2, const float* __restrict__ dh_b2,
    const float* __restrict__ dh_g3, const float* __restrict__ dh_be3,
    const float* __restrict__ dh_w3, const float* __restrict__ dh_b3,
    const float* __restrict__ dr_w1, const float* __restrict__ dr_b1,
    const float* __restrict__ dr_g2, const float* __restrict__ dr_be2,
    const float* __restrict__ dr_w2, const float* __restrict__ dr_b2,
    const float* __restrict__ dr_g3, const float* __restrict__ dr_be3,
    const float* __restrict__ dr_w3, const float* __restrict__ dr_b3,
    float* __restrict__ out) {
    const int b = blockIdx.x;
    const int t = threadIdx.x;          // 128 threads
    __shared__ float xr[D_];
    __shared__ float am[P_];
    __shared__ float h1[128];
    __shared__ float h2[64];
    __shared__ float s_ref_s, s_map_s, mean_s;

    for (int i = t; i < D_; i += 128) xr[i] = q_img[b * D_ + i] - g_famean[i];
    for (int i = t; i < P_; i += 128) am[i] = g_amap[b * P_ + i];
    __syncthreads();

    // ---- dr head on xr (640 -> 128 -> 64 -> 1) ----
    {
        float s = dr_b1[t];
        for (int d = 0; d < D_; ++d) s = fmaf(xr[d], dr_w1[d * 128 + t], s);
        h1[t] = fmaxf(s, 0.f) * dr_g2[t] + dr_be2[t];
    }
    __syncthreads();
    if (t < 64) {
        float s = dr_b2[t];
        for (int i = 0; i < 128; ++i) s = fmaf(h1[i], dr_w2[i * 64 + t], s);
        h2[t] = fmaxf(s, 0.f) * dr_g3[t] + dr_be3[t];
    }
    __syncthreads();
    if (t == 0) {
        float s = dr_b3[0];
        for (int i = 0; i < 64; ++i) s = fmaf(h2[i], dr_w3[i], s);
        s_ref_s = 1.f / (1.f + expf(-s));
    }
    __syncthreads();

    // ---- dh head on am (225 -> 128 -> 64 -> 1) ----
    {
        float s = dh_b1[t];
        for (int p = 0; p < P_; ++p) s = fmaf(am[p], dh_w1[p * 128 + t], s);
        h1[t] = fmaxf(s, 0.f) * dh_g2[t] + dh_be2[t];
    }
    __syncthreads();
    if (t < 64) {
        float s = dh_b2[t];
        for (int i = 0; i < 128; ++i) s = fmaf(h1[i], dh_w2[i * 64 + t], s);
        h2[t] = fmaxf(s, 0.f) * dh_g3[t] + dh_be3[t];
    }
    __syncthreads();
    if (t == 0) {
        float s = dh_b3[0];
        for (int i = 0; i < 64; ++i) s = fmaf(h2[i], dh_w3[i], s);
        s_map_s = 1.f / (1.f + expf(-s));
        float msum = 0.f;
        for (int p = 0; p < P_; ++p) msum += am[p];
        mean_s = msum / (float)P_;
        out[b] = 0.5f * (s_ref_s + s_map_s) + mean_s;
    }
}

// ---------------------------------------------------------------------------
// Launch
// ---------------------------------------------------------------------------
extern "C" void kernel_launch(void* const* d_in, const int* in_sizes, int n_in,
                              void* d_out, int out_size) {
    const float* q_patch = (const float*)d_in[0];
    const float* r_patch = (const float*)d_in[1];
    const float* q_img   = (const float*)d_in[2];
    const float* r_img   = (const float*)d_in[3];
    const float* adpt_w1 = (const float*)d_in[4];
    const float* adpt_w2 = (const float*)d_in[5];
    // dh params: indices 6..15 ; dr params: indices 16..25
    const float* dh_w1  = (const float*)d_in[6];
    const float* dh_b1  = (const float*)d_in[7];
    const float* dh_g2  = (const float*)d_in[8];
    const float* dh_be2 = (const float*)d_in[9];
    const float* dh_w2  = (const float*)d_in[10];
    const float* dh_b2  = (const float*)d_in[11];
    const float* dh_g3  = (const float*)d_in[12];
    const float* dh_be3 = (const float*)d_in[13];
    const float* dh_w3  = (const float*)d_in[14];
    const float* dh_b3  = (const float*)d_in[15];
    const float* dr_w1  = (const float*)d_in[16];
    const float* dr_b1  = (const float*)d_in[17];
    const float* dr_g2  = (const float*)d_in[18];
    const float* dr_be2 = (const float*)d_in[19];
    const float* dr_w2  = (const float*)d_in[20];
    const float* dr_b2  = (const float*)d_in[21];
    const float* dr_g3  = (const float*)d_in[22];
    const float* dr_be3 = (const float*)d_in[23];
    const float* dr_w3  = (const float*)d_in[24];
    const float* dr_b3  = (const float*)d_in[25];
    float* out = (float*)d_out;

    float *qn_ptr = nullptr, *rn_ptr = nullptr;
    cudaGetSymbolAddress((void**)&qn_ptr, g_qn);
    cudaGetSymbolAddress((void**)&rn_ptr, g_rn);

    norm_rows_kernel<<<MQ, 128>>>(q_patch, qn_ptr);
    norm_rows_kernel<<<NR, 128>>>(r_patch, rn_ptr);
    gemm_max_kernel<<<MQ / BM, 256>>>();
    adapter_kernel<<<1, 256>>>(r_img, adpt_w1, adpt_w2);
    heads_kernel<<<B_, 128>>>(q_img,
                              dh_w1, dh_b1, dh_g2, dh_be2, dh_w2, dh_b2,
                              dh_g3, dh_be3, dh_w3, dh_b3,
                              dr_w1, dr_b1, dr_g2, dr_be2, dr_w2, dr_b2,
                              dr_g3, dr_be3, dr_w3, dr_b3,
                              out);
}

// round 4
// speedup vs baseline: 7.9770x; 7.9770x over previous
#include <cuda_runtime.h>
#include <cuda_bf16.h>
#include <math.h>

// ---------------------------------------------------------------------------
// Problem constants
// ---------------------------------------------------------------------------
#define B_   64
#define P_   225
#define K_   16
#define D_   640
#define MQ   (B_ * P_)      // 14400 query rows
#define NR   (K_ * P_)      // 3600 reference rows
#define NRP  3648           // NR padded to 57*64
#define NT_  57             // n tiles of 64

// GEMM tiling
#define BM 64
#define BN 64
#define BK 64
#define LDA 648             // A smem row stride (bf16 elems), pad for banks
#define LDB 72              // B smem row stride
#define NSTRIPE 4

#define A_SMEM_BYTES (BM * LDA * 2)                 // 82944
#define B_SMEM_BYTES (2 * BN * LDB * 2)             // 18432
#define RED_OFF      (A_SMEM_BYTES + B_SMEM_BYTES)  // 101376
#define SMEM_BYTES   (RED_OFF + BM * 5 * 4)         // 102656

// ---------------------------------------------------------------------------
// Scratch (allocation-free: __device__ globals)
// ---------------------------------------------------------------------------
__device__ __nv_bfloat16 g_qb[MQ * D_];     // raw q_patch in bf16
__device__ __nv_bfloat16 g_rb[NRP * D_];    // normalized r_patch in bf16 (padded w/ 0)
__device__ float g_qnorm[MQ];               // ||q_patch row||
__device__ float g_pmax[NSTRIPE * MQ];      // per-stripe max of q.rn
__device__ float g_h1[K_ * 160];            // adapter hidden
__device__ float g_famean[D_];              // mean adapter output

// ---------------------------------------------------------------------------
// Kernel 1: q prep — convert to bf16, compute row norms
// ---------------------------------------------------------------------------
__global__ void prep_q_kernel(const float* __restrict__ in) {
    const int row = blockIdx.x;
    const float* x = in + (size_t)row * D_;
    __nv_bfloat16* o = g_qb + (size_t)row * D_;
    float ss = 0.f;
    for (int i = threadIdx.x; i < D_; i += 128) {
        float v = x[i];
        ss = fmaf(v, v, ss);
        o[i] = __float2bfloat16_rn(v);
    }
    #pragma unroll
    for (int of = 16; of > 0; of >>= 1) ss += __shfl_xor_sync(0xffffffffu, ss, of);
    __shared__ float wsum[4];
    const int lane = threadIdx.x & 31, warp = threadIdx.x >> 5;
    if (lane == 0) wsum[warp] = ss;
    __syncthreads();
    if (threadIdx.x == 0)
        g_qnorm[row] = sqrtf(wsum[0] + wsum[1] + wsum[2] + wsum[3]);
}

// ---------------------------------------------------------------------------
// Kernel 2: r prep — L2 normalize, convert to bf16; zero-fill pad rows
// ---------------------------------------------------------------------------
__global__ void prep_r_kernel(const float* __restrict__ in) {
    const int row = blockIdx.x;
    __nv_bfloat16* o = g_rb + (size_t)row * D_;
    if (row >= NR) {
        for (int i = threadIdx.x; i < D_; i += 128) o[i] = __float2bfloat16_rn(0.f);
        return;
    }
    const float* x = in + (size_t)row * D_;
    float ss = 0.f;
    for (int i = threadIdx.x; i < D_; i += 128) {
        float v = x[i];
        ss = fmaf(v, v, ss);
    }
    #pragma unroll
    for (int of = 16; of > 0; of >>= 1) ss += __shfl_xor_sync(0xffffffffu, ss, of);
    __shared__ float wsum[4];
    const int lane = threadIdx.x & 31, warp = threadIdx.x >> 5;
    if (lane == 0) wsum[warp] = ss;
    __syncthreads();
    const float scale = 1.f / (sqrtf(wsum[0] + wsum[1] + wsum[2] + wsum[3]) + 1e-6f);
    for (int i = threadIdx.x; i < D_; i += 128)
        o[i] = __float2bfloat16_rn(x[i] * scale);
}

// ---------------------------------------------------------------------------
// mma.sync bf16 m16n8k16
// ---------------------------------------------------------------------------
__device__ __forceinline__ void mma16816(float c[4], const unsigned a[4],
                                         const unsigned b[2]) {
    asm volatile(
        "mma.sync.aligned.m16n8k16.row.col.f32.bf16.bf16.f32 "
        "{%0,%1,%2,%3}, {%4,%5,%6,%7}, {%8,%9}, {%0,%1,%2,%3};\n"
        : "+f"(c[0]), "+f"(c[1]), "+f"(c[2]), "+f"(c[3])
        : "r"(a[0]), "r"(a[1]), "r"(a[2]), "r"(a[3]), "r"(b[0]), "r"(b[1]));
}

// ---------------------------------------------------------------------------
// Kernel 3: tensor-core GEMM + row max.
// grid (225, 4): block = 64 q rows, n-stripe = tiles {q, q+4, ...} of BN=64.
// A (64 x 640 bf16) resident in smem; B double-buffered BK=64 stages.
// Writes g_pmax[stripe][row] = max over stripe of q.rn (unnormalized q).
// ---------------------------------------------------------------------------
__global__ __launch_bounds__(256, 2)
void gemm_max_kernel() {
    extern __shared__ char smem[];
    __nv_bfloat16* As = (__nv_bfloat16*)smem;
    __nv_bfloat16* Bs = (__nv_bfloat16*)(smem + A_SMEM_BYTES);
    float* red = (float*)(smem + RED_OFF);

    const int tid  = threadIdx.x;
    const int lane = tid & 31;
    const int g    = lane >> 2;     // group id 0..7
    const int tig  = lane & 3;      // thread-in-group 0..3
    const int w    = tid >> 5;
    const int wy   = w >> 2;        // 0..1 (m)
    const int wx   = w & 3;         // 0..3 (n)
    const int rowBase = blockIdx.x * BM;

    // ---- load full-K A tile: 64 x 640 bf16, uint4 (8 elem) chunks ----
    {
        const __nv_bfloat16* gq = g_qb + (size_t)rowBase * D_;
        #pragma unroll
        for (int i = 0; i < 20; ++i) {
            int idx = tid + i * 256;
            int row = idx / 80, kg = idx % 80;
            *(uint4*)(As + row * LDA + kg * 8) =
                *(const uint4*)(gq + (size_t)row * D_ + kg * 8);
        }
    }
    __syncthreads();

    float rm[2][2] = {{-1e30f, -1e30f}, {-1e30f, -1e30f}};  // [mtile][row g / g+8]

    const int n0 = tid >> 3, kg0 = tid & 7;                   // B ldg/sts idx0
    const int n1 = (tid + 256) >> 3, kg1 = kg0;               // idx1

    for (int nt = blockIdx.y; nt < NT_; nt += NSTRIPE) {
        const int nBase = nt * BN;
        float acc[2][2][4];
        #pragma unroll
        for (int i = 0; i < 2; ++i)
            #pragma unroll
            for (int j = 0; j < 2; ++j)
                #pragma unroll
                for (int r = 0; r < 4; ++r) acc[i][j][r] = 0.f;

        const __nv_bfloat16* gB = g_rb + (size_t)nBase * D_;

        // prologue: stage 0
        {
            uint4 v0 = *(const uint4*)(gB + (size_t)n0 * D_ + kg0 * 8);
            uint4 v1 = *(const uint4*)(gB + (size_t)n1 * D_ + kg1 * 8);
            *(uint4*)(Bs + n0 * LDB + kg0 * 8) = v0;
            *(uint4*)(Bs + n1 * LDB + kg1 * 8) = v1;
        }
        __syncthreads();

        for (int kt = 0; kt < 10; ++kt) {
            uint4 v0, v1;
            if (kt < 9) {
                v0 = *(const uint4*)(gB + (size_t)n0 * D_ + (kt + 1) * BK + kg0 * 8);
                v1 = *(const uint4*)(gB + (size_t)n1 * D_ + (kt + 1) * BK + kg1 * 8);
            }
            const __nv_bfloat16* bufC = Bs + (kt & 1) * BN * LDB;
            const int kA0 = kt * BK;

            #pragma unroll
            for (int ks = 0; ks < 4; ++ks) {
                const int kA = kA0 + ks * 16;
                unsigned a[2][4], b[2][2];
                #pragma unroll
                for (int i = 0; i < 2; ++i) {
                    const __nv_bfloat16* base =
                        As + (wy * 32 + i * 16 + g) * LDA + kA + tig * 2;
                    a[i][0] = *(const unsigned*)(base);
                    a[i][1] = *(const unsigned*)(base + 8 * LDA);
                    a[i][2] = *(const unsigned*)(base + 8);
                    a[i][3] = *(const unsigned*)(base + 8 * LDA + 8);
                }
                #pragma unroll
                for (int j = 0; j < 2; ++j) {
                    const __nv_bfloat16* base =
                        bufC + (wx * 16 + j * 8 + g) * LDB + ks * 16 + tig * 2;
                    b[j][0] = *(const unsigned*)(base);
                    b[j][1] = *(const unsigned*)(base + 8);
                }
                #pragma unroll
                for (int i = 0; i < 2; ++i)
                    #pragma unroll
                    for (int j = 0; j < 2; ++j)
                        mma16816(acc[i][j], a[i], b[j]);
            }

            if (kt < 9) {
                __nv_bfloat16* bufN = Bs + ((kt + 1) & 1) * BN * LDB;
                *(uint4*)(bufN + n0 * LDB + kg0 * 8) = v0;
                *(uint4*)(bufN + n1 * LDB + kg1 * 8) = v1;
                __syncthreads();
            }
        }

        // fold masked max of this n-tile into running max
        #pragma unroll
        for (int j = 0; j < 2; ++j) {
            const int c0 = nBase + wx * 16 + j * 8 + tig * 2;
            const bool v0 = (c0 < NR), v1 = (c0 + 1 < NR);
            #pragma unroll
            for (int i = 0; i < 2; ++i) {
                if (v0) {
                    rm[i][0] = fmaxf(rm[i][0], acc[i][j][0]);
                    rm[i][1] = fmaxf(rm[i][1], acc[i][j][2]);
                }
                if (v1) {
                    rm[i][0] = fmaxf(rm[i][0], acc[i][j][1]);
                    rm[i][1] = fmaxf(rm[i][1], acc[i][j][3]);
                }
            }
        }
        __syncthreads();   // before reusing Bs buffers in next tile's prologue
    }

    // ---- reduce across tig lanes, then across wx warps via smem ----
    #pragma unroll
    for (int i = 0; i < 2; ++i)
        #pragma unroll
        for (int s = 0; s < 2; ++s) {
            float v = rm[i][s];
            v = fmaxf(v, __shfl_xor_sync(0xffffffffu, v, 1));
            v = fmaxf(v, __shfl_xor_sync(0xffffffffu, v, 2));
            rm[i][s] = v;
        }
    if (tig == 0) {
        #pragma unroll
        for (int i = 0; i < 2; ++i)
            #pragma unroll
            for (int s = 0; s < 2; ++s) {
                int row = wy * 32 + i * 16 + s * 8 + g;
                red[row * 5 + wx] = rm[i][s];
            }
    }
    __syncthreads();
    if (tid < BM) {
        float m = red[tid * 5 + 0];
        m = fmaxf(m, red[tid * 5 + 1]);
        m = fmaxf(m, red[tid * 5 + 2]);
        m = fmaxf(m, red[tid * 5 + 3]);
        g_pmax[blockIdx.y * MQ + rowBase + tid] = m;
    }
}

// ---------------------------------------------------------------------------
// Kernel 4a: adapter hidden — h1[k][i] = relu(r_img[k] @ w1[:,i]); grid=16
// ---------------------------------------------------------------------------
__global__ void adapter_h1_kernel(const float* __restrict__ r_img,
                                  const float* __restrict__ w1) {
    const int k = blockIdx.x;
    const int i = threadIdx.x;            // 160 threads
    __shared__ float xr[D_];
    for (int d = threadIdx.x; d < D_; d += 160) xr[d] = r_img[k * D_ + d];
    __syncthreads();
    float s0 = 0.f, s1 = 0.f, s2 = 0.f, s3 = 0.f;
    #pragma unroll 4
    for (int d = 0; d < D_; d += 4) {
        s0 = fmaf(xr[d + 0], w1[(d + 0) * 160 + i], s0);
        s1 = fmaf(xr[d + 1], w1[(d + 1) * 160 + i], s1);
        s2 = fmaf(xr[d + 2], w1[(d + 2) * 160 + i], s2);
        s3 = fmaf(xr[d + 3], w1[(d + 3) * 160 + i], s3);
    }
    g_h1[k * 160 + i] = fmaxf((s0 + s1) + (s2 + s3), 0.f);
}

// ---------------------------------------------------------------------------
// Kernel 4b: famean[j] = mean_k relu(h1[k] @ w2[:,j]); grid=5 x 128
// ---------------------------------------------------------------------------
__global__ void adapter_out_kernel(const float* __restrict__ w2) {
    __shared__ float h1s[K_ * 160];
    for (int idx = threadIdx.x; idx < K_ * 160; idx += 128) h1s[idx] = g_h1[idx];
    __syncthreads();
    const int j = blockIdx.x * 128 + threadIdx.x;
    float accm = 0.f;
    for (int k = 0; k < K_; ++k) {
        float s0 = 0.f, s1 = 0.f;
        const float* h = h1s + k * 160;
        #pragma unroll 4
        for (int i = 0; i < 160; i += 2) {
            s0 = fmaf(h[i], w2[i * D_ + j], s0);
            s1 = fmaf(h[i + 1], w2[(i + 1) * D_ + j], s1);
        }
        accm += fmaxf(s0 + s1, 0.f);
    }
    g_famean[j] = accm * (1.f / (float)K_);
}

// ---------------------------------------------------------------------------
// Kernel 5: both heads + final score; one block per batch element.
// Computes amap from partial maxes + q norms here.
// ---------------------------------------------------------------------------
__global__ void heads_kernel(
    const float* __restrict__ q_img,
    const float* __restrict__ dh_w1, const float* __restrict__ dh_b1,
    const float* __restrict__ dh_g2, const float* __restrict__ dh_be2,
    const float* __restrict__ dh_w2, const float* __restrict__ dh_b2,
    const float* __restrict__ dh_g3, const float* __restrict__ dh_be3,
    const float* __restrict__ dh_w3, const float* __restrict__ dh_b3,
    const float* __restrict__ dr_w1, const float* __restrict__ dr_b1,
    const float* __restrict__ dr_g2, const float* __restrict__ dr_be2,
    const float* __restrict__ dr_w2, const float* __restrict__ dr_b2,
    const float* __restrict__ dr_g3, const float* __restrict__ dr_be3,
    const float* __restrict__ dr_w3, const float* __restrict__ dr_b3,
    float* __restrict__ out) {
    const int b = blockIdx.x;
    const int t = threadIdx.x;          // 128 threads
    __shared__ float xr[D_];
    __shared__ float am[P_];
    __shared__ float h1[128];
    __shared__ float h2[64];
    __shared__ float s_ref_s, s_map_s, mean_s;

    for (int i = t; i < D_; i += 128) xr[i] = q_img[b * D_ + i] - g_famean[i];
    for (int i = t; i < P_; i += 128) {
        const int r = b * P_ + i;
        float mx = g_pmax[r];
        mx = fmaxf(mx, g_pmax[MQ + r]);
        mx = fmaxf(mx, g_pmax[2 * MQ + r]);
        mx = fmaxf(mx, g_pmax[3 * MQ + r]);
        am[i] = 0.5f * (1.f - mx / (g_qnorm[r] + 1e-6f));
    }
    __syncthreads();

    // ---- dr head on xr (640 -> 128 -> 64 -> 1) ----
    {
        float s = dr_b1[t];
        for (int d = 0; d < D_; ++d) s = fmaf(xr[d], dr_w1[d * 128 + t], s);
        h1[t] = fmaxf(s, 0.f) * dr_g2[t] + dr_be2[t];
    }
    __syncthreads();
    if (t < 64) {
        float s = dr_b2[t];
        for (int i = 0; i < 128; ++i) s = fmaf(h1[i], dr_w2[i * 64 + t], s);
        h2[t] = fmaxf(s, 0.f) * dr_g3[t] + dr_be3[t];
    }
    __syncthreads();
    if (t == 0) {
        float s = dr_b3[0];
        for (int i = 0; i < 64; ++i) s = fmaf(h2[i], dr_w3[i], s);
        s_ref_s = 1.f / (1.f + expf(-s));
    }
    __syncthreads();

    // ---- dh head on am (225 -> 128 -> 64 -> 1) ----
    {
        float s = dh_b1[t];
        for (int p = 0; p < P_; ++p) s = fmaf(am[p], dh_w1[p * 128 + t], s);
        h1[t] = fmaxf(s, 0.f) * dh_g2[t] + dh_be2[t];
    }
    __syncthreads();
    if (t < 64) {
        float s = dh_b2[t];
        for (int i = 0; i < 128; ++i) s = fmaf(h1[i], dh_w2[i * 64 + t], s);
        h2[t] = fmaxf(s, 0.f) * dh_g3[t] + dh_be3[t];
    }
    __syncthreads();
    if (t == 0) {
        float s = dh_b3[0];
        for (int i = 0; i < 64; ++i) s = fmaf(h2[i], dh_w3[i], s);
        s_map_s = 1.f / (1.f + expf(-s));
        float msum = 0.f;
        for (int p = 0; p < P_; ++p) msum += am[p];
        mean_s = msum / (float)P_;
        out[b] = 0.5f * (s_ref_s + s_map_s) + mean_s;
    }
}

// ---------------------------------------------------------------------------
// Launch
// ---------------------------------------------------------------------------
extern "C" void kernel_launch(void* const* d_in, const int* in_sizes, int n_in,
                              void* d_out, int out_size) {
    const float* q_patch = (const float*)d_in[0];
    const float* r_patch = (const float*)d_in[1];
    const float* q_img   = (const float*)d_in[2];
    const float* r_img   = (const float*)d_in[3];
    const float* adpt_w1 = (const float*)d_in[4];
    const float* adpt_w2 = (const float*)d_in[5];
    const float* dh_w1  = (const float*)d_in[6];
    const float* dh_b1  = (const float*)d_in[7];
    const float* dh_g2  = (const float*)d_in[8];
    const float* dh_be2 = (const float*)d_in[9];
    const float* dh_w2  = (const float*)d_in[10];
    const float* dh_b2  = (const float*)d_in[11];
    const float* dh_g3  = (const float*)d_in[12];
    const float* dh_be3 = (const float*)d_in[13];
    const float* dh_w3  = (const float*)d_in[14];
    const float* dh_b3  = (const float*)d_in[15];
    const float* dr_w1  = (const float*)d_in[16];
    const float* dr_b1  = (const float*)d_in[17];
    const float* dr_g2  = (const float*)d_in[18];
    const float* dr_be2 = (const float*)d_in[19];
    const float* dr_w2  = (const float*)d_in[20];
    const float* dr_b2  = (const float*)d_in[21];
    const float* dr_g3  = (const float*)d_in[22];
    const float* dr_be3 = (const float*)d_in[23];
    const float* dr_w3  = (const float*)d_in[24];
    const float* dr_b3  = (const float*)d_in[25];
    float* out = (float*)d_out;

    static bool attr_set = false;
    if (!attr_set) {
        cudaFuncSetAttribute(gemm_max_kernel,
                             cudaFuncAttributeMaxDynamicSharedMemorySize,
                             SMEM_BYTES);
        attr_set = true;
    }

    prep_q_kernel<<<MQ, 128>>>(q_patch);
    prep_r_kernel<<<NRP, 128>>>(r_patch);
    gemm_max_kernel<<<dim3(MQ / BM, NSTRIPE), 256, SMEM_BYTES>>>();
    adapter_h1_kernel<<<K_, 160>>>(r_img, adpt_w1);
    adapter_out_kernel<<<D_ / 128, 128>>>(adpt_w2);
    heads_kernel<<<B_, 128>>>(q_img,
                              dh_w1, dh_b1, dh_g2, dh_be2, dh_w2, dh_b2,
                              dh_g3, dh_be3, dh_w3, dh_b3,
                              dr_w1, dr_b1, dr_g2, dr_be2, dr_w2, dr_b2,
                              dr_g3, dr_be3, dr_w3, dr_b3,
                              out);
}